// round 11
// baseline (speedup 1.0000x reference)
#include <cuda_runtime.h>
#include <cuda_bf16.h>
#include <math.h>
#include <cstdint>

// ---------------------------------------------------------------------------
// GGNN layer, GB300. One fused kernel runs the atomic scatter of X and the
// mh split-bf16 HMMA GEMM CONCURRENTLY (disjoint CTA roles, one wave);
// A-operand split (fp32 -> bf16 hi/lo) is done inline in registers.
// Refold: mx = (S·X)@(Wm@gk) + deg·(bm@gk) + b0 ; mh = X@grk + b1
//         out = z*X + (1-z)*tanh(xh + r*rh)
// Precision: A=Ah+Al, B=Bh+Bl (bf16); D = AhBh + AlBh + AhBl (fp32 acc)
// ---------------------------------------------------------------------------

#define D_DIM 128
#define MAXN  50048            // 391*128 tile padding

__device__ float g_Wmg[D_DIM * 384];             // (W1@W2)@gk
__device__ float g_bmg[384];                     // (b1@W2+b2)@gk
__device__ float g_agg[MAXN * D_DIM];            // S·X (zero-padded)
__device__ float g_deg[MAXN];
__device__ float g_mx[MAXN * 3 * D_DIM];
__device__ float g_mh[MAXN * 3 * D_DIM];
// 6 weight tiles (mh x3, mx x3) [n][k] bf16 pairs (linear rows, 256B)
__device__ __align__(16) unsigned int g_BhW[6 * 8192];
__device__ __align__(16) unsigned int g_BlW[6 * 8192];
__device__ float g_biasAll[6 * 128];

// ---------------------------------------------------------------------------
__device__ __forceinline__ uint32_t smem_u32(const void* p) {
    uint32_t a;
    asm("{ .reg .u64 t; cvta.to.shared.u64 t, %1; cvt.u32.u64 %0, t; }"
        : "=r"(a) : "l"(p));
    return a;
}
__device__ __forceinline__ void split2(float2 v, uint32_t& hp, uint32_t& lp) {
    asm("cvt.rn.bf16x2.f32 %0, %1, %2;" : "=r"(hp) : "f"(v.y), "f"(v.x));
    float h0 = __uint_as_float(hp << 16);
    float h1 = __uint_as_float(hp & 0xFFFF0000u);
    asm("cvt.rn.bf16x2.f32 %0, %1, %2;" : "=r"(lp) : "f"(v.y - h1), "f"(v.x - h0));
}
__device__ __forceinline__ void ldsm4(uint32_t& r0, uint32_t& r1, uint32_t& r2,
                                      uint32_t& r3, uint32_t addr) {
    asm volatile("ldmatrix.sync.aligned.m8n8.x4.shared.b16 {%0,%1,%2,%3}, [%4];"
                 : "=r"(r0), "=r"(r1), "=r"(r2), "=r"(r3) : "r"(addr));
}
__device__ __forceinline__ void mma16816(float* c, const uint32_t* a,
                                         const uint32_t* b) {
    asm volatile(
        "mma.sync.aligned.m16n8k16.row.col.f32.bf16.bf16.f32 "
        "{%0,%1,%2,%3}, {%4,%5,%6,%7}, {%8,%9}, {%0,%1,%2,%3};"
        : "+f"(c[0]), "+f"(c[1]), "+f"(c[2]), "+f"(c[3])
        : "r"(a[0]), "r"(a[1]), "r"(a[2]), "r"(a[3]), "r"(b[0]), "r"(b[1]));
}
__device__ __forceinline__ void cpa16(uint32_t dst, const void* src) {
    asm volatile("cp.async.cg.shared.global [%0], [%1], 16;"
                 :: "r"(dst), "l"(src));
}

// ---------------------------------------------------------------------------
// weight folding:  Wmg = (W1@W2)@gk,  bmg = (b1@W2+b2)@gk
// ---------------------------------------------------------------------------
__global__ void __launch_bounds__(384) k_foldA(const float* __restrict__ W1,
                                               const float* __restrict__ W2,
                                               const float* __restrict__ gk) {
    __shared__ float w1r[128], wmr[128];
    int i = blockIdx.x, t = threadIdx.x;
    if (t < 128) w1r[t] = W1[i * 128 + t];
    __syncthreads();
    if (t < 128) {
        float s = 0.f;
#pragma unroll 8
        for (int k = 0; k < 128; k++) s += w1r[k] * W2[k * 128 + t];
        wmr[t] = s;
    }
    __syncthreads();
    float s = 0.f;
#pragma unroll 8
    for (int k = 0; k < 128; k++) s += wmr[k] * gk[k * 384 + t];
    g_Wmg[i * 384 + t] = s;
}

__global__ void __launch_bounds__(384) k_foldB(const float* __restrict__ b1,
                                               const float* __restrict__ W2,
                                               const float* __restrict__ b2,
                                               const float* __restrict__ gk) {
    __shared__ float bmr[128];
    int t = threadIdx.x;
    if (t < 128) {
        float s = b2[t];
        for (int k = 0; k < 128; k++) s += b1[k] * W2[k * 128 + t];
        bmr[t] = s;
    }
    __syncthreads();
    float s = 0.f;
#pragma unroll 8
    for (int k = 0; k < 128; k++) s += bmr[k] * gk[k * 384 + t];
    g_bmg[t] = s;
}

// split weight tiles [n][k] (hi/lo) + biases. j<3: grk (mh); j>=3: Wmg (mx).
__global__ void __launch_bounds__(256)
k_prepW(const float* __restrict__ grk, const float* __restrict__ gb) {
    int j = blockIdx.x, tid = threadIdx.x;
    int n = tid & 127, half = tid >> 7;
    const float* src = (j < 3) ? grk : g_Wmg;
    int c0 = (j % 3) * 128;
    const float* bsrc = gb + ((j < 3) ? 384 : 0) + c0;
    unsigned int* bh = g_BhW + (size_t)j * 8192 + n * 64;
    unsigned int* bl = g_BlW + (size_t)j * 8192 + n * 64;
    for (int k = half * 64; k < half * 64 + 64; k += 2) {
        float2 v = make_float2(src[(size_t)k * 384 + c0 + n],
                               src[(size_t)(k + 1) * 384 + c0 + n]);
        uint32_t hp, lp; split2(v, hp, lp);
        bh[k >> 1] = hp;
        bl[k >> 1] = lp;
    }
    if (half == 0) g_biasAll[j * 128 + n] = bsrc[n];
}

// ---------------------------------------------------------------------------
// zero agg + deg
// ---------------------------------------------------------------------------
__global__ void k_zero(int n4) {
    int i = blockIdx.x * blockDim.x + threadIdx.x;
    if (i < n4) ((float4*)g_agg)[i] = make_float4(0.f, 0.f, 0.f, 0.f);
    if (i < MAXN / 4) ((float4*)g_deg)[i] = make_float4(0.f, 0.f, 0.f, 0.f);
}

// ---------------------------------------------------------------------------
// FUSED kernel.
//  bid <  ngemm : split-bf16 HMMA GEMM worker. j = mode*3 + bid%3,
//                 grid-stride over m-tiles with stride ngemm/3.
//                 A read as fp32 (X if mode 0, g_agg if mode 1), split inline.
//  bid >= ngemm : edge scatter worker (mode 0 launch only): red.v4 of X rows
//                 into g_agg both directions + degree counts.
// ---------------------------------------------------------------------------
#define SM_TOTAL 65536

__global__ void __launch_bounds__(256, 2)
k_fused(const float* __restrict__ X, const int* __restrict__ ra,
        const int* __restrict__ rb, int mode, int Nrow, int E,
        int mtiles, int ngemm) {
    extern __shared__ char smem[];
    const int bid = blockIdx.x;
    const int tid = threadIdx.x, wid = tid >> 5, lane = tid & 31;

    if (bid >= ngemm) {
        // ---------------- scatter branch ----------------
        const int stride = (gridDim.x - ngemm) * 8;
        int w = (bid - ngemm) * 8 + wid;
#pragma unroll 2
        for (int e = w; e < E; e += stride) {
            int a = ra[e], b = rb[e];
            float4 va = ((const float4*)(X + (size_t)a * 128))[lane];
            float4 vb = ((const float4*)(X + (size_t)b * 128))[lane];
            float* pb = g_agg + (size_t)b * 128 + lane * 4;
            float* pa = g_agg + (size_t)a * 128 + lane * 4;
            asm volatile("red.global.add.v4.f32 [%0], {%1,%2,%3,%4};"
                         :: "l"(pb), "f"(va.x), "f"(va.y), "f"(va.z), "f"(va.w)
                         : "memory");
            asm volatile("red.global.add.v4.f32 [%0], {%1,%2,%3,%4};"
                         :: "l"(pa), "f"(vb.x), "f"(vb.y), "f"(vb.z), "f"(vb.w)
                         : "memory");
            if (lane == 0)
                asm volatile("red.global.add.f32 [%0], %1;"
                             :: "l"(g_deg + b), "f"(1.0f) : "memory");
            if (lane == 1)
                asm volatile("red.global.add.f32 [%0], %1;"
                             :: "l"(g_deg + a), "f"(1.0f) : "memory");
        }
        return;
    }

    // ---------------- GEMM branch ----------------
    const uint32_t sb = smem_u32(smem);
    const int j = mode * 3 + (bid % 3);
    const int gi = bid / 3;
    const int gstride = ngemm / 3;

    {   // load B tile once (hi at 0, lo at +32768; chunk c phys = c^(r&7))
        int r = tid >> 1, h = tid & 1;
        const char* s = (const char*)(h ? g_BlW : g_BhW)
                        + (size_t)j * 32768 + (size_t)r * 256;
        uint32_t drow = sb + h * 32768 + r * 256;
        uint32_t rx = (uint32_t)(r & 7);
#pragma unroll
        for (int c = 0; c < 16; c++)
            cpa16(drow + (((uint32_t)c ^ rx) << 4), s + c * 16);
        asm volatile("cp.async.commit_group;" ::: "memory");
        asm volatile("cp.async.wait_group 0;" ::: "memory");
        __syncthreads();
    }

    const int warp_m = wid >> 1, warp_n = wid & 1;
    const int b_row = warp_n * 64 + (lane & 7) + ((lane >> 4) << 3);
    const uint32_t b_rx = (uint32_t)(b_row & 7);
    const int b_sel = (lane >> 3) & 1;
    const uint32_t bBaseHi = sb + b_row * 256;
    const uint32_t bBaseLo = bBaseHi + 32768;

    float* dst = (j < 3) ? g_mh : g_mx;
    const int c0 = (j % 3) * 128;
    const int useDeg = (j >= 3);
    const float* biasG = g_biasAll + j * 128;
    const float* bmgG  = g_bmg + c0;
    const int tr = lane >> 2, tc = (lane & 3) * 2;
    float bx[8], by[8], gx[8], gy[8];
#pragma unroll
    for (int nf = 0; nf < 8; nf++) {
        int col = warp_n * 64 + nf * 8 + tc;
        bx[nf] = biasG[col];
        by[nf] = biasG[col + 1];
        gx[nf] = useDeg ? bmgG[col]     : 0.f;
        gy[nf] = useDeg ? bmgG[col + 1] : 0.f;
    }

    const float* Ab = mode ? g_agg : X;
    const float2 z2 = make_float2(0.f, 0.f);

    for (int mt = gi; mt < mtiles; mt += gstride) {
        float acc[2][8][4];
#pragma unroll
        for (int mf = 0; mf < 2; mf++)
#pragma unroll
            for (int nf = 0; nf < 8; nf++)
#pragma unroll
                for (int q = 0; q < 4; q++) acc[mf][nf][q] = 0.f;

        const int m0 = mt * 128;
        const int rbase = m0 + warp_m * 32 + (lane >> 2);
        const float* pa = Ab + (size_t)rbase * 128 + (lane & 3) * 2;
        const bool ok0 = rbase      < Nrow;
        const bool ok1 = rbase + 8  < Nrow;
        const bool ok2 = rbase + 16 < Nrow;
        const bool ok3 = rbase + 24 < Nrow;

#pragma unroll
        for (int s = 0; s < 8; s++) {
            // inline A load + split (fragment order a0..a3 = v00,v10,v01,v11)
            uint32_t ah0[4], al0[4], ah1[4], al1[4];
            {
                float2 v00 = ok0 ? *(const float2*)(pa + s * 16)          : z2;
                float2 v01 = ok0 ? *(const float2*)(pa + s * 16 + 8)      : z2;
                float2 v10 = ok1 ? *(const float2*)(pa + 1024 + s * 16)   : z2;
                float2 v11 = ok1 ? *(const float2*)(pa + 1024 + s * 16 + 8) : z2;
                split2(v00, ah0[0], al0[0]);
                split2(v10, ah0[1], al0[1]);
                split2(v01, ah0[2], al0[2]);
                split2(v11, ah0[3], al0[3]);
            }
            {
                float2 v00 = ok2 ? *(const float2*)(pa + 2048 + s * 16)     : z2;
                float2 v01 = ok2 ? *(const float2*)(pa + 2048 + s * 16 + 8) : z2;
                float2 v10 = ok3 ? *(const float2*)(pa + 3072 + s * 16)     : z2;
                float2 v11 = ok3 ? *(const float2*)(pa + 3072 + s * 16 + 8) : z2;
                split2(v00, ah1[0], al1[0]);
                split2(v10, ah1[1], al1[1]);
                split2(v01, ah1[2], al1[2]);
                split2(v11, ah1[3], al1[3]);
            }

            uint32_t bfr[16];
            uint32_t lc = (uint32_t)(2 * s + b_sel);
#pragma unroll
            for (int p = 0; p < 4; p++)
                ldsm4(bfr[p * 4], bfr[p * 4 + 1], bfr[p * 4 + 2], bfr[p * 4 + 3],
                      bBaseHi + p * 16 * 256 + ((lc ^ b_rx) << 4));
#pragma unroll
            for (int nf = 0; nf < 8; nf++) {
                const uint32_t* bs = &bfr[(nf >> 1) * 4 + (nf & 1) * 2];
                mma16816(acc[0][nf], ah0, bs);    // Ah*Bh
                mma16816(acc[1][nf], ah1, bs);
                mma16816(acc[0][nf], al0, bs);    // Al*Bh
                mma16816(acc[1][nf], al1, bs);
            }
#pragma unroll
            for (int p = 0; p < 4; p++)
                ldsm4(bfr[p * 4], bfr[p * 4 + 1], bfr[p * 4 + 2], bfr[p * 4 + 3],
                      bBaseLo + p * 16 * 256 + ((lc ^ b_rx) << 4));
#pragma unroll
            for (int nf = 0; nf < 8; nf++) {
                const uint32_t* bs = &bfr[(nf >> 1) * 4 + (nf & 1) * 2];
                mma16816(acc[0][nf], ah0, bs);    // Ah*Bl
                mma16816(acc[1][nf], ah1, bs);
            }
        }

#pragma unroll
        for (int mf = 0; mf < 2; mf++) {
            int row0 = m0 + warp_m * 32 + mf * 16 + tr;
            float dA = useDeg ? g_deg[row0]     : 0.f;
            float dB = useDeg ? g_deg[row0 + 8] : 0.f;
#pragma unroll
            for (int nf = 0; nf < 8; nf++) {
                int col = warp_n * 64 + nf * 8 + tc;
                *(float2*)(dst + (size_t)row0 * 384 + c0 + col) =
                    make_float2(acc[mf][nf][0] + bx[nf] + dA * gx[nf],
                                acc[mf][nf][1] + by[nf] + dA * gy[nf]);
                *(float2*)(dst + (size_t)(row0 + 8) * 384 + c0 + col) =
                    make_float2(acc[mf][nf][2] + bx[nf] + dB * gx[nf],
                                acc[mf][nf][3] + by[nf] + dB * gy[nf]);
            }
        }
    }
}

// ---------------------------------------------------------------------------
__device__ __forceinline__ float sgm(float x) { return 1.f / (1.f + expf(-x)); }

__global__ void __launch_bounds__(256) k_gru(const float* __restrict__ X,
                                             float* __restrict__ out, int n4) {
    int i = blockIdx.x * 256 + threadIdx.x;
    if (i >= n4) return;
    int node = i >> 5, c = i & 31;
    const float4* mx = (const float4*)g_mx + (size_t)node * 96;
    const float4* mh = (const float4*)g_mh + (size_t)node * 96;
    float4 xz = mx[c],      rz = mh[c];
    float4 xr = mx[32 + c], rr = mh[32 + c];
    float4 xh = mx[64 + c], rh = mh[64 + c];
    float4 x  = ((const float4*)X)[i];
    float4 o;
    { float z = sgm(xz.x + rz.x), r = sgm(xr.x + rr.x);
      o.x = z * x.x + (1.f - z) * tanhf(xh.x + r * rh.x); }
    { float z = sgm(xz.y + rz.y), r = sgm(xr.y + rr.y);
      o.y = z * x.y + (1.f - z) * tanhf(xh.y + r * rh.y); }
    { float z = sgm(xz.z + rz.z), r = sgm(xr.z + rr.z);
      o.z = z * x.z + (1.f - z) * tanhf(xh.z + r * rh.z); }
    { float z = sgm(xz.w + rz.w), r = sgm(xr.w + rr.w);
      o.w = z * x.w + (1.f - z) * tanhf(xh.w + r * rh.w); }
    ((float4*)out)[i] = o;
}

// ---------------------------------------------------------------------------
extern "C" void kernel_launch(void* const* d_in, const int* in_sizes, int n_in,
                              void* d_out, int out_size)
{
    const float* X   = (const float*)d_in[0];
    const int*   ra  = (const int*)  d_in[1];
    const int*   rb  = (const int*)  d_in[2];
    const float* W1  = (const float*)d_in[3];
    const float* b1  = (const float*)d_in[4];
    const float* W2  = (const float*)d_in[5];
    const float* b2  = (const float*)d_in[6];
    const float* gk  = (const float*)d_in[7];
    const float* grk = (const float*)d_in[8];
    const float* gb  = (const float*)d_in[9];

    const int N = in_sizes[0] / D_DIM;
    const int E = in_sizes[1];
    const int mtiles = (N + 127) / 128;          // 391

    cudaFuncSetAttribute(k_fused, cudaFuncAttributeMaxDynamicSharedMemorySize,
                         SM_TOTAL);

    // 1-3: weight folding + split weight tiles
    k_foldA<<<128, 384>>>(W1, W2, gk);
    k_foldB<<<1, 384>>>(b1, W2, b2, gk);
    k_prepW<<<6, 256>>>(grk, gb);

    // 4: zero agg + deg
    k_zero<<<(MAXN * 32 + 255) / 256, 256>>>(MAXN * 32);

    // 5 (profiled): FUSED scatter + mh GEMM — one wave, 222 GEMM + 74 scatter
    k_fused<<<296, 256, SM_TOTAL>>>(X, ra, rb, 0, N, E, mtiles, 222);

    // 6: mx GEMM (A = agg inline-split; deg-scaled bias); agg padded -> MAXN
    k_fused<<<294, 256, SM_TOTAL>>>(X, ra, rb, 1, MAXN, E, mtiles, 294);

    // 7: fused GRU update
    k_gru<<<(N * 32 + 255) / 256, 256>>>(X, (float*)d_out, N * 32);
}

// round 12
// speedup vs baseline: 1.3461x; 1.3461x over previous
#include <cuda_runtime.h>
#include <cuda_bf16.h>
#include <math.h>
#include <cstdint>

// ---------------------------------------------------------------------------
// GGNN layer, GB300. R6-proven split-bf16 HMMA GEMM (fragment-major A) +
// concurrent atomic scatter (disjoint CTA roles in one launch).
// Refold: mx_core = (S·X)@(Wm@gk) + b0 ; deg·(bm@gk) added in k_gru.
//         mh = X@grk + b1 ; out = z*X + (1-z)*tanh(xh + r*rh)
// Precision: A=Ah+Al, B=Bh+Bl (bf16); D = AhBh + AlBh + AhBl (fp32 acc)
// ---------------------------------------------------------------------------

#define D_DIM 128
#define MAXN  50048            // 391*128 tile padding
#define MBTOT (MAXN / 16)      // 3128

__device__ float g_Wmg[D_DIM * 384];             // (W1@W2)@gk
__device__ float g_bmg[384];                     // (b1@W2+b2)@gk
__device__ float g_agg[MAXN * D_DIM];            // S·X (zero-padded)
__device__ float g_deg[MAXN];
__device__ float g_mx[MAXN * 3 * D_DIM];
__device__ float g_mh[MAXN * 3 * D_DIM];
// A operands in mma-fragment order: [mb][ks][lane] -> {hi uint4, lo uint4}
__device__ uint4 g_XF[MBTOT * 8 * 32 * 2];
__device__ uint4 g_GF[MBTOT * 8 * 32 * 2];
// 6 weight tiles (mh x3, mx x3) [n][k] bf16 pairs (linear rows, 256B)
__device__ __align__(16) unsigned int g_BhW[6 * 8192];
__device__ __align__(16) unsigned int g_BlW[6 * 8192];
__device__ float g_biasAll[6 * 128];

// ---------------------------------------------------------------------------
__device__ __forceinline__ uint32_t smem_u32(const void* p) {
    uint32_t a;
    asm("{ .reg .u64 t; cvta.to.shared.u64 t, %1; cvt.u32.u64 %0, t; }"
        : "=r"(a) : "l"(p));
    return a;
}
__device__ __forceinline__ void split2(float2 v, uint32_t& hp, uint32_t& lp) {
    asm("cvt.rn.bf16x2.f32 %0, %1, %2;" : "=r"(hp) : "f"(v.y), "f"(v.x));
    float h0 = __uint_as_float(hp << 16);
    float h1 = __uint_as_float(hp & 0xFFFF0000u);
    asm("cvt.rn.bf16x2.f32 %0, %1, %2;" : "=r"(lp) : "f"(v.y - h1), "f"(v.x - h0));
}
__device__ __forceinline__ void ldsm4(uint32_t& r0, uint32_t& r1, uint32_t& r2,
                                      uint32_t& r3, uint32_t addr) {
    asm volatile("ldmatrix.sync.aligned.m8n8.x4.shared.b16 {%0,%1,%2,%3}, [%4];"
                 : "=r"(r0), "=r"(r1), "=r"(r2), "=r"(r3) : "r"(addr));
}
__device__ __forceinline__ void mma16816(float* c, const uint32_t* a,
                                         const uint32_t* b) {
    asm volatile(
        "mma.sync.aligned.m16n8k16.row.col.f32.bf16.bf16.f32 "
        "{%0,%1,%2,%3}, {%4,%5,%6,%7}, {%8,%9}, {%0,%1,%2,%3};"
        : "+f"(c[0]), "+f"(c[1]), "+f"(c[2]), "+f"(c[3])
        : "r"(a[0]), "r"(a[1]), "r"(a[2]), "r"(a[3]), "r"(b[0]), "r"(b[1]));
}
__device__ __forceinline__ void cpa16(uint32_t dst, const void* src) {
    asm volatile("cp.async.cg.shared.global [%0], [%1], 16;"
                 :: "r"(dst), "l"(src));
}

// ---------------------------------------------------------------------------
// weight folding:  Wmg = (W1@W2)@gk,  bmg = (b1@W2+b2)@gk
// ---------------------------------------------------------------------------
__global__ void __launch_bounds__(384) k_foldA(const float* __restrict__ W1,
                                               const float* __restrict__ W2,
                                               const float* __restrict__ gk) {
    __shared__ float w1r[128], wmr[128];
    int i = blockIdx.x, t = threadIdx.x;
    if (t < 128) w1r[t] = W1[i * 128 + t];
    __syncthreads();
    if (t < 128) {
        float s = 0.f;
#pragma unroll 8
        for (int k = 0; k < 128; k++) s += w1r[k] * W2[k * 128 + t];
        wmr[t] = s;
    }
    __syncthreads();
    float s = 0.f;
#pragma unroll 8
    for (int k = 0; k < 128; k++) s += wmr[k] * gk[k * 384 + t];
    g_Wmg[i * 384 + t] = s;
}

__global__ void __launch_bounds__(384) k_foldB(const float* __restrict__ b1,
                                               const float* __restrict__ W2,
                                               const float* __restrict__ b2,
                                               const float* __restrict__ gk) {
    __shared__ float bmr[128];
    int t = threadIdx.x;
    if (t < 128) {
        float s = b2[t];
        for (int k = 0; k < 128; k++) s += b1[k] * W2[k * 128 + t];
        bmr[t] = s;
    }
    __syncthreads();
    float s = 0.f;
#pragma unroll 8
    for (int k = 0; k < 128; k++) s += bmr[k] * gk[k * 384 + t];
    g_bmg[t] = s;
}

// split weight tiles [n][k] (hi/lo) + biases. j<3: grk (mh); j>=3: Wmg (mx).
__global__ void __launch_bounds__(256)
k_prepW(const float* __restrict__ grk, const float* __restrict__ gb) {
    int j = blockIdx.x, tid = threadIdx.x;
    int n = tid & 127, half = tid >> 7;
    const float* src = (j < 3) ? grk : g_Wmg;
    int c0 = (j % 3) * 128;
    const float* bsrc = gb + ((j < 3) ? 384 : 0) + c0;
    unsigned int* bh = g_BhW + (size_t)j * 8192 + n * 64;
    unsigned int* bl = g_BlW + (size_t)j * 8192 + n * 64;
    for (int k = half * 64; k < half * 64 + 64; k += 2) {
        float2 v = make_float2(src[(size_t)k * 384 + c0 + n],
                               src[(size_t)(k + 1) * 384 + c0 + n]);
        uint32_t hp, lp; split2(v, hp, lp);
        bh[k >> 1] = hp;
        bl[k >> 1] = lp;
    }
    if (half == 0) g_biasAll[j * 128 + n] = bsrc[n];
}

// ---------------------------------------------------------------------------
// zero agg + deg
// ---------------------------------------------------------------------------
__global__ void k_zero(int n4) {
    int i = blockIdx.x * blockDim.x + threadIdx.x;
    if (i < n4) ((float4*)g_agg)[i] = make_float4(0.f, 0.f, 0.f, 0.f);
    if (i < MAXN / 4) ((float4*)g_deg)[i] = make_float4(0.f, 0.f, 0.f, 0.f);
}

// ---------------------------------------------------------------------------
// split X into fragment-major hi/lo (g_XF)
// ---------------------------------------------------------------------------
__global__ void __launch_bounds__(256)
k_split(const float* __restrict__ X, int N) {
    int mb = blockIdx.x;
    int ks = threadIdx.x >> 5, lane = threadIdx.x & 31;
    int r0 = mb * 16 + (lane >> 2), r1 = r0 + 8;
    int k0 = ks * 16 + (lane & 3) * 2;
    float2 z2 = make_float2(0.f, 0.f);
    float2 v00 = (r0 < N) ? *(const float2*)(X + (size_t)r0 * 128 + k0)     : z2;
    float2 v01 = (r0 < N) ? *(const float2*)(X + (size_t)r0 * 128 + k0 + 8) : z2;
    float2 v10 = (r1 < N) ? *(const float2*)(X + (size_t)r1 * 128 + k0)     : z2;
    float2 v11 = (r1 < N) ? *(const float2*)(X + (size_t)r1 * 128 + k0 + 8) : z2;
    uint32_t h0, l0, h1, l1, h2, l2, h3, l3;
    split2(v00, h0, l0);
    split2(v10, h1, l1);
    split2(v01, h2, l2);
    split2(v11, h3, l3);
    size_t f = ((size_t)(mb * 8 + ks) * 32 + lane) * 2;
    g_XF[f]     = make_uint4(h0, h1, h2, h3);
    g_XF[f + 1] = make_uint4(l0, l1, l2, l3);
}

// split agg into fragment-major hi/lo (g_GF); agg zero-padded, no guards
__global__ void __launch_bounds__(256)
k_splitAgg(int N) {
    int mb = blockIdx.x;
    int ks = threadIdx.x >> 5, lane = threadIdx.x & 31;
    int r0 = mb * 16 + (lane >> 2), r1 = r0 + 8;
    int k0 = ks * 16 + (lane & 3) * 2;
    const float* A = g_agg;
    float2 v00 = *(const float2*)(A + (size_t)r0 * 128 + k0);
    float2 v01 = *(const float2*)(A + (size_t)r0 * 128 + k0 + 8);
    float2 v10 = *(const float2*)(A + (size_t)r1 * 128 + k0);
    float2 v11 = *(const float2*)(A + (size_t)r1 * 128 + k0 + 8);
    uint32_t h0, l0, h1, l1, h2, l2, h3, l3;
    split2(v00, h0, l0);
    split2(v10, h1, l1);
    split2(v01, h2, l2);
    split2(v11, h3, l3);
    size_t f = ((size_t)(mb * 8 + ks) * 32 + lane) * 2;
    g_GF[f]     = make_uint4(h0, h1, h2, h3);
    g_GF[f + 1] = make_uint4(l0, l1, l2, l3);
}

// ---------------------------------------------------------------------------
// FUSED kernel.
//  bid <  ngemm : R6-style GEMM worker: j = jbase + bid%3, grid-stride over
//                 m-tiles (stride ngemm/3); A = pre-split fragments (XF/GF).
//  bid >= ngemm : edge-scatter worker: red.v4 of X rows into g_agg both
//                 directions + degree counts, grid-stride over edges.
// ---------------------------------------------------------------------------
#define SM_TOTAL 65536

__global__ void __launch_bounds__(256, 2)
k_fused(const float* __restrict__ X, const int* __restrict__ ra,
        const int* __restrict__ rb, int useGF, int jbase, int E,
        int mtiles, int ngemm) {
    extern __shared__ char smem[];
    const int bid = blockIdx.x;
    const int tid = threadIdx.x, wid = tid >> 5, lane = tid & 31;

    if (bid >= ngemm) {
        // ---------------- scatter branch ----------------
        const int nwarp = (gridDim.x - ngemm) * 8;
        int w = (bid - ngemm) * 8 + wid;
        for (int e = w; e < E; e += nwarp * 2) {
            int e2 = e + nwarp;
            int a0i = ra[e], b0i = rb[e];
            int a1i = 0, b1i = 0;
            bool has2 = e2 < E;
            if (has2) { a1i = ra[e2]; b1i = rb[e2]; }
            float4 va0 = ((const float4*)(X + (size_t)a0i * 128))[lane];
            float4 vb0 = ((const float4*)(X + (size_t)b0i * 128))[lane];
            float4 va1, vb1;
            if (has2) {
                va1 = ((const float4*)(X + (size_t)a1i * 128))[lane];
                vb1 = ((const float4*)(X + (size_t)b1i * 128))[lane];
            }
            float* pb0 = g_agg + (size_t)b0i * 128 + lane * 4;
            float* pa0 = g_agg + (size_t)a0i * 128 + lane * 4;
            asm volatile("red.global.add.v4.f32 [%0], {%1,%2,%3,%4};"
                         :: "l"(pb0), "f"(va0.x), "f"(va0.y), "f"(va0.z), "f"(va0.w)
                         : "memory");
            asm volatile("red.global.add.v4.f32 [%0], {%1,%2,%3,%4};"
                         :: "l"(pa0), "f"(vb0.x), "f"(vb0.y), "f"(vb0.z), "f"(vb0.w)
                         : "memory");
            if (lane == 0)
                asm volatile("red.global.add.f32 [%0], %1;"
                             :: "l"(g_deg + b0i), "f"(1.0f) : "memory");
            if (lane == 1)
                asm volatile("red.global.add.f32 [%0], %1;"
                             :: "l"(g_deg + a0i), "f"(1.0f) : "memory");
            if (has2) {
                float* pb1 = g_agg + (size_t)b1i * 128 + lane * 4;
                float* pa1 = g_agg + (size_t)a1i * 128 + lane * 4;
                asm volatile("red.global.add.v4.f32 [%0], {%1,%2,%3,%4};"
                             :: "l"(pb1), "f"(va1.x), "f"(va1.y), "f"(va1.z), "f"(va1.w)
                             : "memory");
                asm volatile("red.global.add.v4.f32 [%0], {%1,%2,%3,%4};"
                             :: "l"(pa1), "f"(vb1.x), "f"(vb1.y), "f"(vb1.z), "f"(vb1.w)
                             : "memory");
                if (lane == 0)
                    asm volatile("red.global.add.f32 [%0], %1;"
                                 :: "l"(g_deg + b1i), "f"(1.0f) : "memory");
                if (lane == 1)
                    asm volatile("red.global.add.f32 [%0], %1;"
                                 :: "l"(g_deg + a1i), "f"(1.0f) : "memory");
            }
        }
        return;
    }

    // ---------------- GEMM branch (R6-proven) ----------------
    const uint32_t sb = smem_u32(smem);
    const int j = jbase + (bid % 3);
    const int gi = bid / 3;
    const int gstride = ngemm / 3;

    {   // load B tile once
        int r = tid >> 1, h = tid & 1;
        const char* s = (const char*)(h ? g_BlW : g_BhW)
                        + (size_t)j * 32768 + (size_t)r * 256;
        uint32_t drow = sb + h * 32768 + r * 256;
        uint32_t rx = (uint32_t)(r & 7);
#pragma unroll
        for (int c = 0; c < 16; c++)
            cpa16(drow + (((uint32_t)c ^ rx) << 4), s + c * 16);
        asm volatile("cp.async.commit_group;" ::: "memory");
        asm volatile("cp.async.wait_group 0;" ::: "memory");
        __syncthreads();
    }

    const int warp_m = wid >> 1, warp_n = wid & 1;
    const int b_row = warp_n * 64 + (lane & 7) + ((lane >> 4) << 3);
    const uint32_t b_rx = (uint32_t)(b_row & 7);
    const int b_sel = (lane >> 3) & 1;
    const uint32_t bBaseHi = sb + b_row * 256;
    const uint32_t bBaseLo = bBaseHi + 32768;

    float* dst = (j < 3) ? g_mh : g_mx;
    const int c0 = (j % 3) * 128;
    const float* biasG = g_biasAll + j * 128;
    const int tr = lane >> 2, tc = (lane & 3) * 2;
    float bx[8], by[8];
#pragma unroll
    for (int nf = 0; nf < 8; nf++) {
        int col = warp_n * 64 + nf * 8 + tc;
        bx[nf] = biasG[col];
        by[nf] = biasG[col + 1];
    }

    const uint4* AF = useGF ? g_GF : g_XF;

    for (int mt = gi; mt < mtiles; mt += gstride) {
        float acc[2][8][4];
#pragma unroll
        for (int mf = 0; mf < 2; mf++)
#pragma unroll
            for (int nf = 0; nf < 8; nf++)
#pragma unroll
                for (int q = 0; q < 4; q++) acc[mf][nf][q] = 0.f;

        const int mbBase = mt * 8 + warp_m * 2;
        const uint4* a0 = AF + (((size_t)mbBase * 8) * 32 + lane) * 2;
        const uint4* a1 = AF + (((size_t)(mbBase + 1) * 8) * 32 + lane) * 2;

#pragma unroll
        for (int s = 0; s < 8; s++) {
            uint4 ahv0 = a0[s * 64], alv0 = a0[s * 64 + 1];
            uint4 ahv1 = a1[s * 64], alv1 = a1[s * 64 + 1];
            const uint32_t* ah0 = &ahv0.x;
            const uint32_t* al0 = &alv0.x;
            const uint32_t* ah1 = &ahv1.x;
            const uint32_t* al1 = &alv1.x;

            uint32_t bfr[16];
            uint32_t lc = (uint32_t)(2 * s + b_sel);
#pragma unroll
            for (int p = 0; p < 4; p++)
                ldsm4(bfr[p * 4], bfr[p * 4 + 1], bfr[p * 4 + 2], bfr[p * 4 + 3],
                      bBaseHi + p * 16 * 256 + ((lc ^ b_rx) << 4));
#pragma unroll
            for (int nf = 0; nf < 8; nf++) {
                const uint32_t* bs = &bfr[(nf >> 1) * 4 + (nf & 1) * 2];
                mma16816(acc[0][nf], ah0, bs);
                mma16816(acc[1][nf], ah1, bs);
                mma16816(acc[0][nf], al0, bs);
                mma16816(acc[1][nf], al1, bs);
            }
#pragma unroll
            for (int p = 0; p < 4; p++)
                ldsm4(bfr[p * 4], bfr[p * 4 + 1], bfr[p * 4 + 2], bfr[p * 4 + 3],
                      bBaseLo + p * 16 * 256 + ((lc ^ b_rx) << 4));
#pragma unroll
            for (int nf = 0; nf < 8; nf++) {
                const uint32_t* bs = &bfr[(nf >> 1) * 4 + (nf & 1) * 2];
                mma16816(acc[0][nf], ah0, bs);
                mma16816(acc[1][nf], ah1, bs);
            }
        }

        const int m0 = mt * 128;
#pragma unroll
        for (int mf = 0; mf < 2; mf++) {
            int row0 = m0 + warp_m * 32 + mf * 16 + tr;
#pragma unroll
            for (int nf = 0; nf < 8; nf++) {
                int col = warp_n * 64 + nf * 8 + tc;
                *(float2*)(dst + (size_t)row0 * 384 + c0 + col) =
                    make_float2(acc[mf][nf][0] + bx[nf], acc[mf][nf][1] + by[nf]);
                *(float2*)(dst + (size_t)(row0 + 8) * 384 + c0 + col) =
                    make_float2(acc[mf][nf][2] + bx[nf], acc[mf][nf][3] + by[nf]);
            }
        }
    }
}

// ---------------------------------------------------------------------------
// fused GRU update; applies the refold's deg*bmg correction to mx gates.
// ---------------------------------------------------------------------------
__device__ __forceinline__ float sgm(float x) { return 1.f / (1.f + expf(-x)); }

__global__ void __launch_bounds__(256) k_gru(const float* __restrict__ X,
                                             float* __restrict__ out, int n4) {
    int i = blockIdx.x * 256 + threadIdx.x;
    if (i >= n4) return;
    int node = i >> 5, c = i & 31;
    const float4* mx = (const float4*)g_mx + (size_t)node * 96;
    const float4* mh = (const float4*)g_mh + (size_t)node * 96;
    const float4* bm = (const float4*)g_bmg;
    float dg = g_deg[node];
    float4 bz = bm[c], brv = bm[32 + c], bhv = bm[64 + c];
    float4 xz = mx[c],      rz = mh[c];
    float4 xr = mx[32 + c], rr = mh[32 + c];
    float4 xh = mx[64 + c], rh = mh[64 + c];
    xz.x += dg * bz.x;  xz.y += dg * bz.y;  xz.z += dg * bz.z;  xz.w += dg * bz.w;
    xr.x += dg * brv.x; xr.y += dg * brv.y; xr.z += dg * brv.z; xr.w += dg * brv.w;
    xh.x += dg * bhv.x; xh.y += dg * bhv.y; xh.z += dg * bhv.z; xh.w += dg * bhv.w;
    float4 x = ((const float4*)X)[i];
    float4 o;
    { float z = sgm(xz.x + rz.x), r = sgm(xr.x + rr.x);
      o.x = z * x.x + (1.f - z) * tanhf(xh.x + r * rh.x); }
    { float z = sgm(xz.y + rz.y), r = sgm(xr.y + rr.y);
      o.y = z * x.y + (1.f - z) * tanhf(xh.y + r * rh.y); }
    { float z = sgm(xz.z + rz.z), r = sgm(xr.z + rr.z);
      o.z = z * x.z + (1.f - z) * tanhf(xh.z + r * rh.z); }
    { float z = sgm(xz.w + rz.w), r = sgm(xr.w + rr.w);
      o.w = z * x.w + (1.f - z) * tanhf(xh.w + r * rh.w); }
    ((float4*)out)[i] = o;
}

// ---------------------------------------------------------------------------
extern "C" void kernel_launch(void* const* d_in, const int* in_sizes, int n_in,
                              void* d_out, int out_size)
{
    const float* X   = (const float*)d_in[0];
    const int*   ra  = (const int*)  d_in[1];
    const int*   rb  = (const int*)  d_in[2];
    const float* W1  = (const float*)d_in[3];
    const float* b1  = (const float*)d_in[4];
    const float* W2  = (const float*)d_in[5];
    const float* b2  = (const float*)d_in[6];
    const float* gk  = (const float*)d_in[7];
    const float* grk = (const float*)d_in[8];
    const float* gb  = (const float*)d_in[9];

    const int N = in_sizes[0] / D_DIM;
    const int E = in_sizes[1];
    const int mtiles = (N + 127) / 128;          // 391
    const int mbtot  = mtiles * 8;               // 3128

    cudaFuncSetAttribute(k_fused, cudaFuncAttributeMaxDynamicSharedMemorySize,
                         SM_TOTAL);

    // 1-3: weight folding + split weight tiles
    k_foldA<<<128, 384>>>(W1, W2, gk);
    k_foldB<<<1, 384>>>(b1, W2, b2, gk);
    k_prepW<<<6, 256>>>(grk, gb);

    // 4: zero agg + deg
    k_zero<<<(MAXN * 32 + 255) / 256, 256>>>(MAXN * 32);

    // 5: split X -> XF
    k_split<<<mbtot, 256>>>(X, N);

    // 6 (profiled): FUSED scatter (74 CTAs) + mh GEMM (222 CTAs, A=XF)
    k_fused<<<296, 256, SM_TOTAL>>>(X, ra, rb, 0, 0, E, mtiles, 222);

    // 7: split agg -> GF
    k_splitAgg<<<mbtot, 256>>>(N);

    // 8: mx GEMM (294 CTAs, A=GF, no scatter CTAs)
    k_fused<<<294, 256, SM_TOTAL>>>(X, ra, rb, 1, 3, E, mtiles, 294);

    // 9: fused GRU update (+ deg*bmg refold correction)
    k_gru<<<(N * 32 + 255) / 256, 256>>>(X, (float*)d_out, N * 32);
}

// round 13
// speedup vs baseline: 2.8177x; 2.0932x over previous
#include <cuda_runtime.h>
#include <cuda_bf16.h>
#include <math.h>
#include <cstdint>

// ---------------------------------------------------------------------------
// GGNN layer, GB300. R6-proven split-bf16 HMMA GEMMs + one-edge-per-warp
// atomic scatter. Refold: mx_core = (S·X)@(Wm@gk) + b0, with the deg·(bm@gk)
// term applied in the GRU epilogue; deg from a separate int histogram.
//   mh = X@grk + b1 ; out = z*X + (1-z)*tanh(xh + r*rh)
// Precision: A=Ah+Al, B=Bh+Bl (bf16); D = AhBh + AlBh + AhBl (fp32 acc)
// ---------------------------------------------------------------------------

#define D_DIM 128
#define MAXN  50048            // 391*128 tile padding
#define MBTOT (MAXN / 16)      // 3128

__device__ float g_Wmg[D_DIM * 384];             // (W1@W2)@gk
__device__ float g_bmg[384];                     // (b1@W2+b2)@gk
__device__ float g_agg[MAXN * D_DIM];            // S·X (zero-padded)
__device__ int   g_cnt[MAXN];                    // degree
__device__ float g_mx[MAXN * 3 * D_DIM];
__device__ float g_mh[MAXN * 3 * D_DIM];
// A operands in mma-fragment order: [mb][ks][lane] -> {hi uint4, lo uint4}
__device__ uint4 g_XF[MBTOT * 8 * 32 * 2];
__device__ uint4 g_GF[MBTOT * 8 * 32 * 2];
// 6 weight tiles (mh x3, mx x3) [n][k] bf16 pairs (linear rows, 256B)
__device__ __align__(16) unsigned int g_BhW[6 * 8192];
__device__ __align__(16) unsigned int g_BlW[6 * 8192];
__device__ float g_biasAll[6 * 128];

// ---------------------------------------------------------------------------
__device__ __forceinline__ uint32_t smem_u32(const void* p) {
    uint32_t a;
    asm("{ .reg .u64 t; cvta.to.shared.u64 t, %1; cvt.u32.u64 %0, t; }"
        : "=r"(a) : "l"(p));
    return a;
}
__device__ __forceinline__ void split2(float2 v, uint32_t& hp, uint32_t& lp) {
    asm("cvt.rn.bf16x2.f32 %0, %1, %2;" : "=r"(hp) : "f"(v.y), "f"(v.x));
    float h0 = __uint_as_float(hp << 16);
    float h1 = __uint_as_float(hp & 0xFFFF0000u);
    asm("cvt.rn.bf16x2.f32 %0, %1, %2;" : "=r"(lp) : "f"(v.y - h1), "f"(v.x - h0));
}
__device__ __forceinline__ void ldsm4(uint32_t& r0, uint32_t& r1, uint32_t& r2,
                                      uint32_t& r3, uint32_t addr) {
    asm volatile("ldmatrix.sync.aligned.m8n8.x4.shared.b16 {%0,%1,%2,%3}, [%4];"
                 : "=r"(r0), "=r"(r1), "=r"(r2), "=r"(r3) : "r"(addr));
}
__device__ __forceinline__ void mma16816(float* c, const uint32_t* a,
                                         const uint32_t* b) {
    asm volatile(
        "mma.sync.aligned.m16n8k16.row.col.f32.bf16.bf16.f32 "
        "{%0,%1,%2,%3}, {%4,%5,%6,%7}, {%8,%9}, {%0,%1,%2,%3};"
        : "+f"(c[0]), "+f"(c[1]), "+f"(c[2]), "+f"(c[3])
        : "r"(a[0]), "r"(a[1]), "r"(a[2]), "r"(a[3]), "r"(b[0]), "r"(b[1]));
}
__device__ __forceinline__ void cpa16(uint32_t dst, const void* src) {
    asm volatile("cp.async.cg.shared.global [%0], [%1], 16;"
                 :: "r"(dst), "l"(src));
}

// ---------------------------------------------------------------------------
// weight folding:  Wmg = (W1@W2)@gk,  bmg = (b1@W2+b2)@gk
// ---------------------------------------------------------------------------
__global__ void __launch_bounds__(384) k_foldA(const float* __restrict__ W1,
                                               const float* __restrict__ W2,
                                               const float* __restrict__ gk) {
    __shared__ float w1r[128], wmr[128];
    int i = blockIdx.x, t = threadIdx.x;
    if (t < 128) w1r[t] = W1[i * 128 + t];
    __syncthreads();
    if (t < 128) {
        float s = 0.f;
#pragma unroll 8
        for (int k = 0; k < 128; k++) s += w1r[k] * W2[k * 128 + t];
        wmr[t] = s;
    }
    __syncthreads();
    float s = 0.f;
#pragma unroll 8
    for (int k = 0; k < 128; k++) s += wmr[k] * gk[k * 384 + t];
    g_Wmg[i * 384 + t] = s;
}

__global__ void __launch_bounds__(384) k_foldB(const float* __restrict__ b1,
                                               const float* __restrict__ W2,
                                               const float* __restrict__ b2,
                                               const float* __restrict__ gk) {
    __shared__ float bmr[128];
    int t = threadIdx.x;
    if (t < 128) {
        float s = b2[t];
        for (int k = 0; k < 128; k++) s += b1[k] * W2[k * 128 + t];
        bmr[t] = s;
    }
    __syncthreads();
    float s = 0.f;
#pragma unroll 8
    for (int k = 0; k < 128; k++) s += bmr[k] * gk[k * 384 + t];
    g_bmg[t] = s;
}

// split weight tiles [n][k] (hi/lo) + biases. j<3: grk (mh); j>=3: Wmg (mx).
__global__ void __launch_bounds__(256)
k_prepW(const float* __restrict__ grk, const float* __restrict__ gb) {
    int j = blockIdx.x, tid = threadIdx.x;
    int n = tid & 127, half = tid >> 7;
    const float* src = (j < 3) ? grk : g_Wmg;
    int c0 = (j % 3) * 128;
    const float* bsrc = gb + ((j < 3) ? 384 : 0) + c0;
    unsigned int* bh = g_BhW + (size_t)j * 8192 + n * 64;
    unsigned int* bl = g_BlW + (size_t)j * 8192 + n * 64;
    for (int k = half * 64; k < half * 64 + 64; k += 2) {
        float2 v = make_float2(src[(size_t)k * 384 + c0 + n],
                               src[(size_t)(k + 1) * 384 + c0 + n]);
        uint32_t hp, lp; split2(v, hp, lp);
        bh[k >> 1] = hp;
        bl[k >> 1] = lp;
    }
    if (half == 0) g_biasAll[j * 128 + n] = bsrc[n];
}

// ---------------------------------------------------------------------------
// zero agg + degree counters
// ---------------------------------------------------------------------------
__global__ void k_zero(int n4) {
    int i = blockIdx.x * blockDim.x + threadIdx.x;
    if (i < n4) ((float4*)g_agg)[i] = make_float4(0.f, 0.f, 0.f, 0.f);
    if (i < MAXN) g_cnt[i] = 0;
}

// degree histogram (int atomics, spread addresses — cheap)
__global__ void k_hist(const int* __restrict__ ra, const int* __restrict__ rb,
                       int E) {
    int e = blockIdx.x * blockDim.x + threadIdx.x;
    if (e >= E) return;
    atomicAdd(&g_cnt[ra[e]], 1);
    atomicAdd(&g_cnt[rb[e]], 1);
}

// ---------------------------------------------------------------------------
// undirected scatter-add of X rows: one edge per warp, red.v4 both ways.
// (R6-proven structure: MLP comes from the CTA wave, no in-warp loop.)
// ---------------------------------------------------------------------------
__global__ void __launch_bounds__(256)
k_scatter(const float* __restrict__ X, const int* __restrict__ ra,
          const int* __restrict__ rb, int E) {
    int w    = (blockIdx.x * 256 + threadIdx.x) >> 5;
    int lane = threadIdx.x & 31;
    if (w >= E) return;
    int a = ra[w];
    int b = rb[w];
    float4 va = ((const float4*)(X + (size_t)a * 128))[lane];
    float4 vb = ((const float4*)(X + (size_t)b * 128))[lane];
    float* pb = g_agg + (size_t)b * 128 + lane * 4;
    float* pa = g_agg + (size_t)a * 128 + lane * 4;
    asm volatile("red.global.add.v4.f32 [%0], {%1,%2,%3,%4};"
                 :: "l"(pb), "f"(va.x), "f"(va.y), "f"(va.z), "f"(va.w) : "memory");
    asm volatile("red.global.add.v4.f32 [%0], {%1,%2,%3,%4};"
                 :: "l"(pa), "f"(vb.x), "f"(vb.y), "f"(vb.z), "f"(vb.w) : "memory");
}

// ---------------------------------------------------------------------------
// split X into fragment-major hi/lo (g_XF)
// ---------------------------------------------------------------------------
__global__ void __launch_bounds__(256)
k_split(const float* __restrict__ X, int N) {
    int mb = blockIdx.x;
    int ks = threadIdx.x >> 5, lane = threadIdx.x & 31;
    int r0 = mb * 16 + (lane >> 2), r1 = r0 + 8;
    int k0 = ks * 16 + (lane & 3) * 2;
    float2 z2 = make_float2(0.f, 0.f);
    float2 v00 = (r0 < N) ? *(const float2*)(X + (size_t)r0 * 128 + k0)     : z2;
    float2 v01 = (r0 < N) ? *(const float2*)(X + (size_t)r0 * 128 + k0 + 8) : z2;
    float2 v10 = (r1 < N) ? *(const float2*)(X + (size_t)r1 * 128 + k0)     : z2;
    float2 v11 = (r1 < N) ? *(const float2*)(X + (size_t)r1 * 128 + k0 + 8) : z2;
    uint32_t h0, l0, h1, l1, h2, l2, h3, l3;
    split2(v00, h0, l0);
    split2(v10, h1, l1);
    split2(v01, h2, l2);
    split2(v11, h3, l3);
    size_t f = ((size_t)(mb * 8 + ks) * 32 + lane) * 2;
    g_XF[f]     = make_uint4(h0, h1, h2, h3);
    g_XF[f + 1] = make_uint4(l0, l1, l2, l3);
}

// split agg into fragment-major hi/lo (g_GF); agg zero-padded, no guards
__global__ void __launch_bounds__(256)
k_splitAgg(int N) {
    int mb = blockIdx.x;
    int ks = threadIdx.x >> 5, lane = threadIdx.x & 31;
    int r0 = mb * 16 + (lane >> 2), r1 = r0 + 8;
    int k0 = ks * 16 + (lane & 3) * 2;
    const float* A = g_agg;
    float2 v00 = *(const float2*)(A + (size_t)r0 * 128 + k0);
    float2 v01 = *(const float2*)(A + (size_t)r0 * 128 + k0 + 8);
    float2 v10 = *(const float2*)(A + (size_t)r1 * 128 + k0);
    float2 v11 = *(const float2*)(A + (size_t)r1 * 128 + k0 + 8);
    uint32_t h0, l0, h1, l1, h2, l2, h3, l3;
    split2(v00, h0, l0);
    split2(v10, h1, l1);
    split2(v01, h2, l2);
    split2(v11, h3, l3);
    size_t f = ((size_t)(mb * 8 + ks) * 32 + lane) * 2;
    g_GF[f]     = make_uint4(h0, h1, h2, h3);
    g_GF[f + 1] = make_uint4(l0, l1, l2, l3);
}

// ---------------------------------------------------------------------------
// persistent split-bf16 HMMA GEMM (R6-proven; barrier-free inner loop,
// B tile loaded once). j = jbase + blockIdx.y; A = XF (mh) or GF (mx).
// ---------------------------------------------------------------------------
#define SM_TOTAL 65536

__global__ void __launch_bounds__(256, 2)
k_mmagemm(int useGF, int jbase, int mtiles) {
    extern __shared__ char smem[];
    const uint32_t sb = smem_u32(smem);
    const int tid = threadIdx.x, wid = tid >> 5, lane = tid & 31;
    const int j = jbase + blockIdx.y;

    {   // load B tile once
        int r = tid >> 1, h = tid & 1;
        const char* s = (const char*)(h ? g_BlW : g_BhW)
                        + (size_t)j * 32768 + (size_t)r * 256;
        uint32_t drow = sb + h * 32768 + r * 256;
        uint32_t rx = (uint32_t)(r & 7);
#pragma unroll
        for (int c = 0; c < 16; c++)
            cpa16(drow + (((uint32_t)c ^ rx) << 4), s + c * 16);
        asm volatile("cp.async.commit_group;" ::: "memory");
        asm volatile("cp.async.wait_group 0;" ::: "memory");
        __syncthreads();
    }

    const int warp_m = wid >> 1, warp_n = wid & 1;
    const int b_row = warp_n * 64 + (lane & 7) + ((lane >> 4) << 3);
    const uint32_t b_rx = (uint32_t)(b_row & 7);
    const int b_sel = (lane >> 3) & 1;
    const uint32_t bBaseHi = sb + b_row * 256;
    const uint32_t bBaseLo = bBaseHi + 32768;

    float* dst = (j < 3) ? g_mh : g_mx;
    const int c0 = (j % 3) * 128;
    const float* biasG = g_biasAll + j * 128;
    const int tr = lane >> 2, tc = (lane & 3) * 2;
    float bx[8], by[8];
#pragma unroll
    for (int nf = 0; nf < 8; nf++) {
        int col = warp_n * 64 + nf * 8 + tc;
        bx[nf] = biasG[col];
        by[nf] = biasG[col + 1];
    }

    const uint4* AF = useGF ? g_GF : g_XF;

    for (int mt = blockIdx.x; mt < mtiles; mt += gridDim.x) {
        float acc[2][8][4];
#pragma unroll
        for (int mf = 0; mf < 2; mf++)
#pragma unroll
            for (int nf = 0; nf < 8; nf++)
#pragma unroll
                for (int q = 0; q < 4; q++) acc[mf][nf][q] = 0.f;

        const int mbBase = mt * 8 + warp_m * 2;
        const uint4* a0 = AF + (((size_t)mbBase * 8) * 32 + lane) * 2;
        const uint4* a1 = AF + (((size_t)(mbBase + 1) * 8) * 32 + lane) * 2;

#pragma unroll
        for (int s = 0; s < 8; s++) {
            uint4 ahv0 = a0[s * 64], alv0 = a0[s * 64 + 1];
            uint4 ahv1 = a1[s * 64], alv1 = a1[s * 64 + 1];
            const uint32_t* ah0 = &ahv0.x;
            const uint32_t* al0 = &alv0.x;
            const uint32_t* ah1 = &ahv1.x;
            const uint32_t* al1 = &alv1.x;

            uint32_t bfr[16];
            uint32_t lc = (uint32_t)(2 * s + b_sel);
#pragma unroll
            for (int p = 0; p < 4; p++)
                ldsm4(bfr[p * 4], bfr[p * 4 + 1], bfr[p * 4 + 2], bfr[p * 4 + 3],
                      bBaseHi + p * 16 * 256 + ((lc ^ b_rx) << 4));
#pragma unroll
            for (int nf = 0; nf < 8; nf++) {
                const uint32_t* bs = &bfr[(nf >> 1) * 4 + (nf & 1) * 2];
                mma16816(acc[0][nf], ah0, bs);
                mma16816(acc[1][nf], ah1, bs);
                mma16816(acc[0][nf], al0, bs);
                mma16816(acc[1][nf], al1, bs);
            }
#pragma unroll
            for (int p = 0; p < 4; p++)
                ldsm4(bfr[p * 4], bfr[p * 4 + 1], bfr[p * 4 + 2], bfr[p * 4 + 3],
                      bBaseLo + p * 16 * 256 + ((lc ^ b_rx) << 4));
#pragma unroll
            for (int nf = 0; nf < 8; nf++) {
                const uint32_t* bs = &bfr[(nf >> 1) * 4 + (nf & 1) * 2];
                mma16816(acc[0][nf], ah0, bs);
                mma16816(acc[1][nf], ah1, bs);
            }
        }

        const int m0 = mt * 128;
#pragma unroll
        for (int mf = 0; mf < 2; mf++) {
            int row0 = m0 + warp_m * 32 + mf * 16 + tr;
#pragma unroll
            for (int nf = 0; nf < 8; nf++) {
                int col = warp_n * 64 + nf * 8 + tc;
                *(float2*)(dst + (size_t)row0 * 384 + c0 + col) =
                    make_float2(acc[mf][nf][0] + bx[nf], acc[mf][nf][1] + by[nf]);
                *(float2*)(dst + (size_t)(row0 + 8) * 384 + c0 + col) =
                    make_float2(acc[mf][nf][2] + bx[nf], acc[mf][nf][3] + by[nf]);
            }
        }
    }
}

// ---------------------------------------------------------------------------
// fused GRU update; applies the refold's deg*bmg correction to mx gates.
// ---------------------------------------------------------------------------
__device__ __forceinline__ float sgm(float x) { return 1.f / (1.f + expf(-x)); }

__global__ void __launch_bounds__(256) k_gru(const float* __restrict__ X,
                                             float* __restrict__ out, int n4) {
    int i = blockIdx.x * 256 + threadIdx.x;
    if (i >= n4) return;
    int node = i >> 5, c = i & 31;
    const float4* mx = (const float4*)g_mx + (size_t)node * 96;
    const float4* mh = (const float4*)g_mh + (size_t)node * 96;
    const float4* bm = (const float4*)g_bmg;
    float dg = (float)g_cnt[node];
    float4 bz = bm[c], brv = bm[32 + c], bhv = bm[64 + c];
    float4 xz = mx[c],      rz = mh[c];
    float4 xr = mx[32 + c], rr = mh[32 + c];
    float4 xh = mx[64 + c], rh = mh[64 + c];
    xz.x += dg * bz.x;  xz.y += dg * bz.y;  xz.z += dg * bz.z;  xz.w += dg * bz.w;
    xr.x += dg * brv.x; xr.y += dg * brv.y; xr.z += dg * brv.z; xr.w += dg * brv.w;
    xh.x += dg * bhv.x; xh.y += dg * bhv.y; xh.z += dg * bhv.z; xh.w += dg * bhv.w;
    float4 x = ((const float4*)X)[i];
    float4 o;
    { float z = sgm(xz.x + rz.x), r = sgm(xr.x + rr.x);
      o.x = z * x.x + (1.f - z) * tanhf(xh.x + r * rh.x); }
    { float z = sgm(xz.y + rz.y), r = sgm(xr.y + rr.y);
      o.y = z * x.y + (1.f - z) * tanhf(xh.y + r * rh.y); }
    { float z = sgm(xz.z + rz.z), r = sgm(xr.z + rr.z);
      o.z = z * x.z + (1.f - z) * tanhf(xh.z + r * rh.z); }
    { float z = sgm(xz.w + rz.w), r = sgm(xr.w + rr.w);
      o.w = z * x.w + (1.f - z) * tanhf(xh.w + r * rh.w); }
    ((float4*)out)[i] = o;
}

// ---------------------------------------------------------------------------
extern "C" void kernel_launch(void* const* d_in, const int* in_sizes, int n_in,
                              void* d_out, int out_size)
{
    const float* X   = (const float*)d_in[0];
    const int*   ra  = (const int*)  d_in[1];
    const int*   rb  = (const int*)  d_in[2];
    const float* W1  = (const float*)d_in[3];
    const float* b1  = (const float*)d_in[4];
    const float* W2  = (const float*)d_in[5];
    const float* b2  = (const float*)d_in[6];
    const float* gk  = (const float*)d_in[7];
    const float* grk = (const float*)d_in[8];
    const float* gb  = (const float*)d_in[9];

    const int N = in_sizes[0] / D_DIM;
    const int E = in_sizes[1];
    const int mtiles = (N + 127) / 128;          // 391
    const int mbtot  = mtiles * 8;               // 3128

    cudaFuncSetAttribute(k_mmagemm, cudaFuncAttributeMaxDynamicSharedMemorySize,
                         SM_TOTAL);

    // 1-3: weight folding + split weight tiles
    k_foldA<<<128, 384>>>(W1, W2, gk);
    k_foldB<<<1, 384>>>(b1, W2, b2, gk);
    k_prepW<<<6, 256>>>(grk, gb);

    // 4: zero agg + cnt
    k_zero<<<(MAXN * 32 + 255) / 256, 256>>>(MAXN * 32);

    // 5: split X -> XF
    k_split<<<mbtot, 256>>>(X, N);

    // 6 (profiled): degree histogram
    k_hist<<<(E + 255) / 256, 256>>>(ra, rb, E);

    // 7: undirected scatter of X rows (one edge per warp, R6 structure)
    k_scatter<<<(E + 7) / 8, 256>>>(X, ra, rb, E);

    // 8: mh GEMM (A = XF)
    k_mmagemm<<<dim3(98, 3), 256, SM_TOTAL>>>(0, 0, mtiles);

    // 9: split agg -> GF
    k_splitAgg<<<mbtot, 256>>>(N);

    // 10: mx GEMM (A = GF)
    k_mmagemm<<<dim3(98, 3), 256, SM_TOTAL>>>(1, 3, mtiles);

    // 11: fused GRU update (+ deg*bmg refold correction)
    k_gru<<<(N * 32 + 255) / 256, 256>>>(X, (float*)d_out, N * 32);
}

// round 14
// speedup vs baseline: 2.8741x; 1.0200x over previous
#include <cuda_runtime.h>
#include <cuda_bf16.h>
#include <math.h>
#include <cstdint>

// ---------------------------------------------------------------------------
// GGNN layer, GB300. R6-proven split-bf16 HMMA GEMMs + one-edge-per-warp
// atomic scatter, with the scatter branch forked onto a second stream so it
// overlaps the mh GEMM chain inside the captured graph.
// Refold: mx_core = (S·X)@(Wm@gk) + b0 ; deg·(bm@gk) applied in k_gru.
//   mh = X@grk + b1 ; out = z*X + (1-z)*tanh(xh + r*rh)
// Precision: A=Ah+Al, B=Bh+Bl (bf16); D = AhBh + AlBh + AhBl (fp32 acc)
// ---------------------------------------------------------------------------

#define D_DIM 128
#define MAXN  50048            // 391*128 tile padding
#define MBTOT (MAXN / 16)      // 3128

__device__ float g_Wmg[D_DIM * 384];             // (W1@W2)@gk
__device__ float g_bmg[384];                     // (b1@W2+b2)@gk
__device__ float g_agg[MAXN * D_DIM];            // S·X (zero-padded)
__device__ int   g_cnt[MAXN];                    // degree
__device__ float g_mx[MAXN * 3 * D_DIM];
__device__ float g_mh[MAXN * 3 * D_DIM];
// A operands in mma-fragment order: [mb][ks][lane] -> {hi uint4, lo uint4}
__device__ uint4 g_XF[MBTOT * 8 * 32 * 2];
__device__ uint4 g_GF[MBTOT * 8 * 32 * 2];
// 6 weight tiles (mh x3, mx x3) [n][k] bf16 pairs (linear rows, 256B)
__device__ __align__(16) unsigned int g_BhW[6 * 8192];
__device__ __align__(16) unsigned int g_BlW[6 * 8192];
__device__ float g_biasAll[6 * 128];

// ---------------------------------------------------------------------------
__device__ __forceinline__ uint32_t smem_u32(const void* p) {
    uint32_t a;
    asm("{ .reg .u64 t; cvta.to.shared.u64 t, %1; cvt.u32.u64 %0, t; }"
        : "=r"(a) : "l"(p));
    return a;
}
__device__ __forceinline__ void split2(float2 v, uint32_t& hp, uint32_t& lp) {
    asm("cvt.rn.bf16x2.f32 %0, %1, %2;" : "=r"(hp) : "f"(v.y), "f"(v.x));
    float h0 = __uint_as_float(hp << 16);
    float h1 = __uint_as_float(hp & 0xFFFF0000u);
    asm("cvt.rn.bf16x2.f32 %0, %1, %2;" : "=r"(lp) : "f"(v.y - h1), "f"(v.x - h0));
}
__device__ __forceinline__ void ldsm4(uint32_t& r0, uint32_t& r1, uint32_t& r2,
                                      uint32_t& r3, uint32_t addr) {
    asm volatile("ldmatrix.sync.aligned.m8n8.x4.shared.b16 {%0,%1,%2,%3}, [%4];"
                 : "=r"(r0), "=r"(r1), "=r"(r2), "=r"(r3) : "r"(addr));
}
__device__ __forceinline__ void mma16816(float* c, const uint32_t* a,
                                         const uint32_t* b) {
    asm volatile(
        "mma.sync.aligned.m16n8k16.row.col.f32.bf16.bf16.f32 "
        "{%0,%1,%2,%3}, {%4,%5,%6,%7}, {%8,%9}, {%0,%1,%2,%3};"
        : "+f"(c[0]), "+f"(c[1]), "+f"(c[2]), "+f"(c[3])
        : "r"(a[0]), "r"(a[1]), "r"(a[2]), "r"(a[3]), "r"(b[0]), "r"(b[1]));
}
__device__ __forceinline__ void cpa16(uint32_t dst, const void* src) {
    asm volatile("cp.async.cg.shared.global [%0], [%1], 16;"
                 :: "r"(dst), "l"(src));
}

// ---------------------------------------------------------------------------
// weight folding:  Wmg = (W1@W2)@gk,  bmg = (b1@W2+b2)@gk
// ---------------------------------------------------------------------------
__global__ void __launch_bounds__(384) k_foldA(const float* __restrict__ W1,
                                               const float* __restrict__ W2,
                                               const float* __restrict__ gk) {
    __shared__ float w1r[128], wmr[128];
    int i = blockIdx.x, t = threadIdx.x;
    if (t < 128) w1r[t] = W1[i * 128 + t];
    __syncthreads();
    if (t < 128) {
        float s = 0.f;
#pragma unroll 8
        for (int k = 0; k < 128; k++) s += w1r[k] * W2[k * 128 + t];
        wmr[t] = s;
    }
    __syncthreads();
    float s = 0.f;
#pragma unroll 8
    for (int k = 0; k < 128; k++) s += wmr[k] * gk[k * 384 + t];
    g_Wmg[i * 384 + t] = s;
}

__global__ void __launch_bounds__(384) k_foldB(const float* __restrict__ b1,
                                               const float* __restrict__ W2,
                                               const float* __restrict__ b2,
                                               const float* __restrict__ gk) {
    __shared__ float bmr[128];
    int t = threadIdx.x;
    if (t < 128) {
        float s = b2[t];
        for (int k = 0; k < 128; k++) s += b1[k] * W2[k * 128 + t];
        bmr[t] = s;
    }
    __syncthreads();
    float s = 0.f;
#pragma unroll 8
    for (int k = 0; k < 128; k++) s += bmr[k] * gk[k * 384 + t];
    g_bmg[t] = s;
}

// split weight tiles [n][k] (hi/lo) + biases. j<3: grk (mh); j>=3: Wmg (mx).
__global__ void __launch_bounds__(256)
k_prepW(const float* __restrict__ grk, const float* __restrict__ gb) {
    int j = blockIdx.x, tid = threadIdx.x;
    int n = tid & 127, half = tid >> 7;
    const float* src = (j < 3) ? grk : g_Wmg;
    int c0 = (j % 3) * 128;
    const float* bsrc = gb + ((j < 3) ? 384 : 0) + c0;
    unsigned int* bh = g_BhW + (size_t)j * 8192 + n * 64;
    unsigned int* bl = g_BlW + (size_t)j * 8192 + n * 64;
    for (int k = half * 64; k < half * 64 + 64; k += 2) {
        float2 v = make_float2(src[(size_t)k * 384 + c0 + n],
                               src[(size_t)(k + 1) * 384 + c0 + n]);
        uint32_t hp, lp; split2(v, hp, lp);
        bh[k >> 1] = hp;
        bl[k >> 1] = lp;
    }
    if (half == 0) g_biasAll[j * 128 + n] = bsrc[n];
}

// ---------------------------------------------------------------------------
// zero agg + degree counters
// ---------------------------------------------------------------------------
__global__ void k_zero(int n4) {
    int i = blockIdx.x * blockDim.x + threadIdx.x;
    if (i < n4) ((float4*)g_agg)[i] = make_float4(0.f, 0.f, 0.f, 0.f);
    if (i < MAXN) g_cnt[i] = 0;
}

// degree histogram (int atomics, spread addresses — cheap)
__global__ void k_hist(const int* __restrict__ ra, const int* __restrict__ rb,
                       int E) {
    int e = blockIdx.x * blockDim.x + threadIdx.x;
    if (e >= E) return;
    atomicAdd(&g_cnt[ra[e]], 1);
    atomicAdd(&g_cnt[rb[e]], 1);
}

// ---------------------------------------------------------------------------
// undirected scatter-add of X rows: one edge per warp, red.v4 both ways.
// ---------------------------------------------------------------------------
__global__ void __launch_bounds__(256)
k_scatter(const float* __restrict__ X, const int* __restrict__ ra,
          const int* __restrict__ rb, int E) {
    int w    = (blockIdx.x * 256 + threadIdx.x) >> 5;
    int lane = threadIdx.x & 31;
    if (w >= E) return;
    int a = ra[w];
    int b = rb[w];
    float4 va = ((const float4*)(X + (size_t)a * 128))[lane];
    float4 vb = ((const float4*)(X + (size_t)b * 128))[lane];
    float* pb = g_agg + (size_t)b * 128 + lane * 4;
    float* pa = g_agg + (size_t)a * 128 + lane * 4;
    asm volatile("red.global.add.v4.f32 [%0], {%1,%2,%3,%4};"
                 :: "l"(pb), "f"(va.x), "f"(va.y), "f"(va.z), "f"(va.w) : "memory");
    asm volatile("red.global.add.v4.f32 [%0], {%1,%2,%3,%4};"
                 :: "l"(pa), "f"(vb.x), "f"(vb.y), "f"(vb.z), "f"(vb.w) : "memory");
}

// ---------------------------------------------------------------------------
// split X into fragment-major hi/lo (g_XF)
// ---------------------------------------------------------------------------
__global__ void __launch_bounds__(256)
k_split(const float* __restrict__ X, int N) {
    int mb = blockIdx.x;
    int ks = threadIdx.x >> 5, lane = threadIdx.x & 31;
    int r0 = mb * 16 + (lane >> 2), r1 = r0 + 8;
    int k0 = ks * 16 + (lane & 3) * 2;
    float2 z2 = make_float2(0.f, 0.f);
    float2 v00 = (r0 < N) ? *(const float2*)(X + (size_t)r0 * 128 + k0)     : z2;
    float2 v01 = (r0 < N) ? *(const float2*)(X + (size_t)r0 * 128 + k0 + 8) : z2;
    float2 v10 = (r1 < N) ? *(const float2*)(X + (size_t)r1 * 128 + k0)     : z2;
    float2 v11 = (r1 < N) ? *(const float2*)(X + (size_t)r1 * 128 + k0 + 8) : z2;
    uint32_t h0, l0, h1, l1, h2, l2, h3, l3;
    split2(v00, h0, l0);
    split2(v10, h1, l1);
    split2(v01, h2, l2);
    split2(v11, h3, l3);
    size_t f = ((size_t)(mb * 8 + ks) * 32 + lane) * 2;
    g_XF[f]     = make_uint4(h0, h1, h2, h3);
    g_XF[f + 1] = make_uint4(l0, l1, l2, l3);
}

// split agg into fragment-major hi/lo (g_GF); agg zero-padded, no guards
__global__ void __launch_bounds__(256)
k_splitAgg(int N) {
    int mb = blockIdx.x;
    int ks = threadIdx.x >> 5, lane = threadIdx.x & 31;
    int r0 = mb * 16 + (lane >> 2), r1 = r0 + 8;
    int k0 = ks * 16 + (lane & 3) * 2;
    const float* A = g_agg;
    float2 v00 = *(const float2*)(A + (size_t)r0 * 128 + k0);
    float2 v01 = *(const float2*)(A + (size_t)r0 * 128 + k0 + 8);
    float2 v10 = *(const float2*)(A + (size_t)r1 * 128 + k0);
    float2 v11 = *(const float2*)(A + (size_t)r1 * 128 + k0 + 8);
    uint32_t h0, l0, h1, l1, h2, l2, h3, l3;
    split2(v00, h0, l0);
    split2(v10, h1, l1);
    split2(v01, h2, l2);
    split2(v11, h3, l3);
    size_t f = ((size_t)(mb * 8 + ks) * 32 + lane) * 2;
    g_GF[f]     = make_uint4(h0, h1, h2, h3);
    g_GF[f + 1] = make_uint4(l0, l1, l2, l3);
}

// ---------------------------------------------------------------------------
// persistent split-bf16 HMMA GEMM (R6-proven; barrier-free inner loop,
// B tile loaded once). j = jbase + blockIdx.y; A = XF (mh) or GF (mx).
// ---------------------------------------------------------------------------
#define SM_TOTAL 65536

__global__ void __launch_bounds__(256, 2)
k_mmagemm(int useGF, int jbase, int mtiles) {
    extern __shared__ char smem[];
    const uint32_t sb = smem_u32(smem);
    const int tid = threadIdx.x, wid = tid >> 5, lane = tid & 31;
    const int j = jbase + blockIdx.y;

    {   // load B tile once
        int r = tid >> 1, h = tid & 1;
        const char* s = (const char*)(h ? g_BlW : g_BhW)
                        + (size_t)j * 32768 + (size_t)r * 256;
        uint32_t drow = sb + h * 32768 + r * 256;
        uint32_t rx = (uint32_t)(r & 7);
#pragma unroll
        for (int c = 0; c < 16; c++)
            cpa16(drow + (((uint32_t)c ^ rx) << 4), s + c * 16);
        asm volatile("cp.async.commit_group;" ::: "memory");
        asm volatile("cp.async.wait_group 0;" ::: "memory");
        __syncthreads();
    }

    const int warp_m = wid >> 1, warp_n = wid & 1;
    const int b_row = warp_n * 64 + (lane & 7) + ((lane >> 4) << 3);
    const uint32_t b_rx = (uint32_t)(b_row & 7);
    const int b_sel = (lane >> 3) & 1;
    const uint32_t bBaseHi = sb + b_row * 256;
    const uint32_t bBaseLo = bBaseHi + 32768;

    float* dst = (j < 3) ? g_mh : g_mx;
    const int c0 = (j % 3) * 128;
    const float* biasG = g_biasAll + j * 128;
    const int tr = lane >> 2, tc = (lane & 3) * 2;
    float bx[8], by[8];
#pragma unroll
    for (int nf = 0; nf < 8; nf++) {
        int col = warp_n * 64 + nf * 8 + tc;
        bx[nf] = biasG[col];
        by[nf] = biasG[col + 1];
    }

    const uint4* AF = useGF ? g_GF : g_XF;

    for (int mt = blockIdx.x; mt < mtiles; mt += gridDim.x) {
        float acc[2][8][4];
#pragma unroll
        for (int mf = 0; mf < 2; mf++)
#pragma unroll
            for (int nf = 0; nf < 8; nf++)
#pragma unroll
                for (int q = 0; q < 4; q++) acc[mf][nf][q] = 0.f;

        const int mbBase = mt * 8 + warp_m * 2;
        const uint4* a0 = AF + (((size_t)mbBase * 8) * 32 + lane) * 2;
        const uint4* a1 = AF + (((size_t)(mbBase + 1) * 8) * 32 + lane) * 2;

#pragma unroll
        for (int s = 0; s < 8; s++) {
            uint4 ahv0 = a0[s * 64], alv0 = a0[s * 64 + 1];
            uint4 ahv1 = a1[s * 64], alv1 = a1[s * 64 + 1];
            const uint32_t* ah0 = &ahv0.x;
            const uint32_t* al0 = &alv0.x;
            const uint32_t* ah1 = &ahv1.x;
            const uint32_t* al1 = &alv1.x;

            uint32_t bfr[16];
            uint32_t lc = (uint32_t)(2 * s + b_sel);
#pragma unroll
            for (int p = 0; p < 4; p++)
                ldsm4(bfr[p * 4], bfr[p * 4 + 1], bfr[p * 4 + 2], bfr[p * 4 + 3],
                      bBaseHi + p * 16 * 256 + ((lc ^ b_rx) << 4));
#pragma unroll
            for (int nf = 0; nf < 8; nf++) {
                const uint32_t* bs = &bfr[(nf >> 1) * 4 + (nf & 1) * 2];
                mma16816(acc[0][nf], ah0, bs);
                mma16816(acc[1][nf], ah1, bs);
                mma16816(acc[0][nf], al0, bs);
                mma16816(acc[1][nf], al1, bs);
            }
#pragma unroll
            for (int p = 0; p < 4; p++)
                ldsm4(bfr[p * 4], bfr[p * 4 + 1], bfr[p * 4 + 2], bfr[p * 4 + 3],
                      bBaseLo + p * 16 * 256 + ((lc ^ b_rx) << 4));
#pragma unroll
            for (int nf = 0; nf < 8; nf++) {
                const uint32_t* bs = &bfr[(nf >> 1) * 4 + (nf & 1) * 2];
                mma16816(acc[0][nf], ah0, bs);
                mma16816(acc[1][nf], ah1, bs);
            }
        }

        const int m0 = mt * 128;
#pragma unroll
        for (int mf = 0; mf < 2; mf++) {
            int row0 = m0 + warp_m * 32 + mf * 16 + tr;
#pragma unroll
            for (int nf = 0; nf < 8; nf++) {
                int col = warp_n * 64 + nf * 8 + tc;
                *(float2*)(dst + (size_t)row0 * 384 + c0 + col) =
                    make_float2(acc[mf][nf][0] + bx[nf], acc[mf][nf][1] + by[nf]);
                *(float2*)(dst + (size_t)(row0 + 8) * 384 + c0 + col) =
                    make_float2(acc[mf][nf][2] + bx[nf], acc[mf][nf][3] + by[nf]);
            }
        }
    }
}

// ---------------------------------------------------------------------------
// fused GRU update; applies the refold's deg*bmg correction to mx gates.
// ---------------------------------------------------------------------------
__device__ __forceinline__ float sgm(float x) { return 1.f / (1.f + expf(-x)); }

__global__ void __launch_bounds__(256) k_gru(const float* __restrict__ X,
                                             float* __restrict__ out, int n4) {
    int i = blockIdx.x * 256 + threadIdx.x;
    if (i >= n4) return;
    int node = i >> 5, c = i & 31;
    const float4* mx = (const float4*)g_mx + (size_t)node * 96;
    const float4* mh = (const float4*)g_mh + (size_t)node * 96;
    const float4* bm = (const float4*)g_bmg;
    float dg = (float)g_cnt[node];
    float4 bz = bm[c], brv = bm[32 + c], bhv = bm[64 + c];
    float4 xz = mx[c],      rz = mh[c];
    float4 xr = mx[32 + c], rr = mh[32 + c];
    float4 xh = mx[64 + c], rh = mh[64 + c];
    xz.x += dg * bz.x;  xz.y += dg * bz.y;  xz.z += dg * bz.z;  xz.w += dg * bz.w;
    xr.x += dg * brv.x; xr.y += dg * brv.y; xr.z += dg * brv.z; xr.w += dg * brv.w;
    xh.x += dg * bhv.x; xh.y += dg * bhv.y; xh.z += dg * bhv.z; xh.w += dg * bhv.w;
    float4 x = ((const float4*)X)[i];
    float4 o;
    { float z = sgm(xz.x + rz.x), r = sgm(xr.x + rr.x);
      o.x = z * x.x + (1.f - z) * tanhf(xh.x + r * rh.x); }
    { float z = sgm(xz.y + rz.y), r = sgm(xr.y + rr.y);
      o.y = z * x.y + (1.f - z) * tanhf(xh.y + r * rh.y); }
    { float z = sgm(xz.z + rz.z), r = sgm(xr.z + rr.z);
      o.z = z * x.z + (1.f - z) * tanhf(xh.z + r * rh.z); }
    { float z = sgm(xz.w + rz.w), r = sgm(xr.w + rr.w);
      o.w = z * x.w + (1.f - z) * tanhf(xh.w + r * rh.w); }
    ((float4*)out)[i] = o;
}

// ---------------------------------------------------------------------------
extern "C" void kernel_launch(void* const* d_in, const int* in_sizes, int n_in,
                              void* d_out, int out_size)
{
    const float* X   = (const float*)d_in[0];
    const int*   ra  = (const int*)  d_in[1];
    const int*   rb  = (const int*)  d_in[2];
    const float* W1  = (const float*)d_in[3];
    const float* b1  = (const float*)d_in[4];
    const float* W2  = (const float*)d_in[5];
    const float* b2  = (const float*)d_in[6];
    const float* gk  = (const float*)d_in[7];
    const float* grk = (const float*)d_in[8];
    const float* gb  = (const float*)d_in[9];

    const int N = in_sizes[0] / D_DIM;
    const int E = in_sizes[1];
    const int mtiles = (N + 127) / 128;          // 391
    const int mbtot  = mtiles * 8;               // 3128

    // one-time (first call is the uncaptured correctness pass)
    static cudaStream_t s2 = nullptr;
    static cudaEvent_t  evF = nullptr, evJ = nullptr;
    if (s2 == nullptr) {
        cudaStreamCreateWithFlags(&s2, cudaStreamNonBlocking);
        cudaEventCreateWithFlags(&evF, cudaEventDisableTiming);
        cudaEventCreateWithFlags(&evJ, cudaEventDisableTiming);
        cudaFuncSetAttribute(k_mmagemm,
                             cudaFuncAttributeMaxDynamicSharedMemorySize,
                             SM_TOTAL);
    }

    // 1-4: weight folding + split weight tiles + zero (legacy stream)
    k_foldA<<<128, 384>>>(W1, W2, gk);
    k_foldB<<<1, 384>>>(b1, W2, b2, gk);
    k_prepW<<<6, 256>>>(grk, gb);
    k_zero<<<(MAXN * 32 + 255) / 256, 256>>>(MAXN * 32);

    // fork: scatter branch on s2 (independent of GEMM chain after refold)
    cudaEventRecord(evF, 0);
    cudaStreamWaitEvent(s2, evF, 0);
    k_hist<<<(E + 255) / 256, 256, 0, s2>>>(ra, rb, E);
    k_scatter<<<(E + 7) / 8, 256, 0, s2>>>(X, ra, rb, E);
    cudaEventRecord(evJ, s2);

    // legacy branch, concurrent with scatter: split X + mh GEMM
    k_split<<<mbtot, 256>>>(X, N);
    k_mmagemm<<<dim3(98, 3), 256, SM_TOTAL>>>(0, 0, mtiles);

    // join: mx chain needs the completed agg
    cudaStreamWaitEvent(0, evJ, 0);

    // split agg -> GF, mx GEMM, GRU epilogue
    k_splitAgg<<<mbtot, 256>>>(N);
    k_mmagemm<<<dim3(98, 3), 256, SM_TOTAL>>>(1, 3, mtiles);
    k_gru<<<(N * 32 + 255) / 256, 256>>>(X, (float*)d_out, N * 32);
}